// round 3
// baseline (speedup 1.0000x reference)
#include <cuda_runtime.h>
#include <math.h>
#include <stdint.h>

#define N_TOK 4096
#define H_DIM 1024
#define F_DIM 4096
#define N_EXP 8

#define BM 128
#define BN 128
#define BK 32
#define NTHREADS 256
#define TILES_PER_E (N_TOK / BM)  // 32

#define AS_STRIDE 40    // BK + 8 -> bank(8*gid+tig) all distinct, 16B-aligned rows
#define BS_STRIDE 136   // BN + 8 -> bank(8*tig+gid) all distinct, 16B-aligned rows

// Routing state + h scratch (allocation-free: __device__ globals).
__device__ int   g_cnt[N_EXP];
__device__ int   g_off[N_EXP];
__device__ int   g_tok[N_EXP * N_TOK];
__device__ float g_gw [N_EXP * N_TOK];
__device__ float g_h[(size_t)9216 * F_DIM];

__device__ __forceinline__ uint32_t f2tf32(float f) {
    uint32_t r;
    asm("cvt.rna.tf32.f32 %0, %1;" : "=r"(r) : "f"(f));
    return r;
}

__device__ __forceinline__ void mma_tf32(float c[4],
                                         uint32_t a0, uint32_t a1, uint32_t a2, uint32_t a3,
                                         uint32_t b0, uint32_t b1) {
    asm volatile(
        "mma.sync.aligned.m16n8k8.row.col.f32.tf32.tf32.f32 "
        "{%0,%1,%2,%3}, {%4,%5,%6,%7}, {%8,%9}, {%0,%1,%2,%3};\n"
        : "+f"(c[0]), "+f"(c[1]), "+f"(c[2]), "+f"(c[3])
        : "r"(a0), "r"(a1), "r"(a2), "r"(a3), "r"(b0), "r"(b1));
}

__global__ void zero_kernel(float* __restrict__ out, int n) {
    int i = blockIdx.x * blockDim.x + threadIdx.x;
    if (i < N_EXP) g_cnt[i] = 0;
    int stride = gridDim.x * blockDim.x;
    for (int j = i; j < n; j += stride) out[j] = 0.0f;
}

__global__ void gate_kernel(const float* __restrict__ x,
                            const float* __restrict__ Wg,
                            const float* __restrict__ bg) {
    int warp = threadIdx.x >> 5;
    int lane = threadIdx.x & 31;
    int n = blockIdx.x * (blockDim.x >> 5) + warp;
    if (n >= N_TOK) return;

    float acc[N_EXP];
#pragma unroll
    for (int e = 0; e < N_EXP; e++) acc[e] = 0.0f;

    const float* xr = x + (size_t)n * H_DIM;
    for (int h = lane; h < H_DIM; h += 32) {
        float xv = xr[h];
        const float4 w0 = *reinterpret_cast<const float4*>(Wg + h * N_EXP);
        const float4 w1 = *reinterpret_cast<const float4*>(Wg + h * N_EXP + 4);
        acc[0] += xv * w0.x; acc[1] += xv * w0.y;
        acc[2] += xv * w0.z; acc[3] += xv * w0.w;
        acc[4] += xv * w1.x; acc[5] += xv * w1.y;
        acc[6] += xv * w1.z; acc[7] += xv * w1.w;
    }
#pragma unroll
    for (int e = 0; e < N_EXP; e++) {
#pragma unroll
        for (int o = 16; o > 0; o >>= 1)
            acc[e] += __shfl_xor_sync(0xffffffffu, acc[e], o);
    }

    if (lane == 0) {
        float lg[N_EXP];
        float m = -1e30f;
#pragma unroll
        for (int e = 0; e < N_EXP; e++) {
            lg[e] = acc[e] + bg[e];
            m = fmaxf(m, lg[e]);
        }
        float s = 0.0f;
        float p[N_EXP];
#pragma unroll
        for (int e = 0; e < N_EXP; e++) { p[e] = expf(lg[e] - m); s += p[e]; }
        float inv = 1.0f / s;
#pragma unroll
        for (int e = 0; e < N_EXP; e++) p[e] *= inv;

        int i0 = 0;
#pragma unroll
        for (int e = 1; e < N_EXP; e++) if (p[e] > p[i0]) i0 = e;
        int i1 = (i0 == 0) ? 1 : 0;
#pragma unroll
        for (int e = 0; e < N_EXP; e++)
            if (e != i0 && p[e] > p[i1]) i1 = e;

        int pos0 = atomicAdd(&g_cnt[i0], 1);
        g_tok[i0 * N_TOK + pos0] = n;
        g_gw [i0 * N_TOK + pos0] = p[i0];
        int pos1 = atomicAdd(&g_cnt[i1], 1);
        g_tok[i1 * N_TOK + pos1] = n;
        g_gw [i1 * N_TOK + pos1] = p[i1];
    }
}

__global__ void offsets_kernel() {
    if (threadIdx.x == 0 && blockIdx.x == 0) {
        int off = 0;
        for (int e = 0; e < N_EXP; e++) {
            g_off[e] = off;
            off += ((g_cnt[e] + BM - 1) / BM) * BM;
        }
    }
}

// ---------------------------------------------------------------------------
// ffn1: h = gelu(X_gathered @ W1[e] + b1[e]) -> g_h   (K = H_DIM)
// ---------------------------------------------------------------------------
__global__ __launch_bounds__(NTHREADS) void ffn1_kernel(
    const float* __restrict__ x,
    const float* __restrict__ W1,
    const float* __restrict__ b1) {
    int e    = blockIdx.y / TILES_PER_E;
    int tile = blockIdx.y % TILES_PER_E;
    int row0 = tile * BM;
    int cnt  = g_cnt[e];
    if (row0 >= cnt) return;
    int off  = g_off[e];
    int col0 = blockIdx.x * BN;
    const float* B = W1 + (size_t)e * H_DIM * F_DIM;

    __shared__ uint32_t As[BM * AS_STRIDE];
    __shared__ uint32_t Bs[BK * BS_STRIDE];
    __shared__ int toks[BM];

    int tid = threadIdx.x;
    if (tid < BM) {
        int r = row0 + tid;
        if (r >= cnt) r = cnt - 1;
        toks[tid] = g_tok[e * N_TOK + r];
    }
    __syncthreads();

    int warp = tid >> 5, lane = tid & 31;
    int gid = lane >> 2, tig = lane & 3;
    int wm = (warp >> 2) * 64, wn = (warp & 3) * 32;

    float acc[4][4][4];
#pragma unroll
    for (int mf = 0; mf < 4; mf++)
#pragma unroll
        for (int nf = 0; nf < 4; nf++)
#pragma unroll
            for (int r = 0; r < 4; r++) acc[mf][nf][r] = 0.0f;

    int a_r = tid >> 3, a_c = (tid & 7) * 4;     // A f4 slots: rows a_r+32i
    int b_r = tid >> 5, b_c = (tid & 31) * 4;    // B f4 slots: rows b_r+8i

    float4 rA[4], rB[4];

    // prefetch k-tile 0
#pragma unroll
    for (int i = 0; i < 4; i++) {
        rA[i] = *reinterpret_cast<const float4*>(x + (size_t)toks[a_r + i * 32] * H_DIM + a_c);
        rB[i] = *reinterpret_cast<const float4*>(B + (size_t)(b_r + i * 8) * F_DIM + col0 + b_c);
    }
#pragma unroll
    for (int i = 0; i < 4; i++) {
        uint4 va = {f2tf32(rA[i].x), f2tf32(rA[i].y), f2tf32(rA[i].z), f2tf32(rA[i].w)};
        *reinterpret_cast<uint4*>(&As[(a_r + i * 32) * AS_STRIDE + a_c]) = va;
        uint4 vb = {f2tf32(rB[i].x), f2tf32(rB[i].y), f2tf32(rB[i].z), f2tf32(rB[i].w)};
        *reinterpret_cast<uint4*>(&Bs[(b_r + i * 8) * BS_STRIDE + b_c]) = vb;
    }
    __syncthreads();

    const int NKT = H_DIM / BK;
    for (int kt = 0; kt < NKT; kt++) {
        bool more = (kt + 1 < NKT);
        if (more) {
            int k0 = (kt + 1) * BK;
#pragma unroll
            for (int i = 0; i < 4; i++) {
                rA[i] = *reinterpret_cast<const float4*>(x + (size_t)toks[a_r + i * 32] * H_DIM + k0 + a_c);
                rB[i] = *reinterpret_cast<const float4*>(B + (size_t)(k0 + b_r + i * 8) * F_DIM + col0 + b_c);
            }
        }
#pragma unroll
        for (int ks = 0; ks < 4; ks++) {
            int k = ks * 8;
            uint32_t af[4][4], bf[4][2];
#pragma unroll
            for (int mf = 0; mf < 4; mf++) {
                int m = wm + mf * 16 + gid;
                af[mf][0] = As[m * AS_STRIDE + k + tig];
                af[mf][1] = As[(m + 8) * AS_STRIDE + k + tig];
                af[mf][2] = As[m * AS_STRIDE + k + tig + 4];
                af[mf][3] = As[(m + 8) * AS_STRIDE + k + tig + 4];
            }
#pragma unroll
            for (int nf = 0; nf < 4; nf++) {
                int n = wn + nf * 8 + gid;
                bf[nf][0] = Bs[(k + tig) * BS_STRIDE + n];
                bf[nf][1] = Bs[(k + tig + 4) * BS_STRIDE + n];
            }
#pragma unroll
            for (int mf = 0; mf < 4; mf++)
#pragma unroll
                for (int nf = 0; nf < 4; nf++)
                    mma_tf32(acc[mf][nf], af[mf][0], af[mf][1], af[mf][2], af[mf][3],
                             bf[nf][0], bf[nf][1]);
        }
        if (more) {
            __syncthreads();
#pragma unroll
            for (int i = 0; i < 4; i++) {
                uint4 va = {f2tf32(rA[i].x), f2tf32(rA[i].y), f2tf32(rA[i].z), f2tf32(rA[i].w)};
                *reinterpret_cast<uint4*>(&As[(a_r + i * 32) * AS_STRIDE + a_c]) = va;
                uint4 vb = {f2tf32(rB[i].x), f2tf32(rB[i].y), f2tf32(rB[i].z), f2tf32(rB[i].w)};
                *reinterpret_cast<uint4*>(&Bs[(b_r + i * 8) * BS_STRIDE + b_c]) = vb;
            }
            __syncthreads();
        }
    }

    // epilogue: bias + exact gelu -> g_h
#pragma unroll
    for (int mf = 0; mf < 4; mf++) {
#pragma unroll
        for (int r2 = 0; r2 < 2; r2++) {
            int m = wm + mf * 16 + gid + r2 * 8;
            float* hrow = g_h + (size_t)(off + row0 + m) * F_DIM + col0;
#pragma unroll
            for (int nf = 0; nf < 4; nf++) {
                int c = wn + nf * 8 + tig * 2;
                float v0 = acc[mf][nf][r2 * 2 + 0] + b1[e * F_DIM + col0 + c];
                float v1 = acc[mf][nf][r2 * 2 + 1] + b1[e * F_DIM + col0 + c + 1];
                float2 g;
                g.x = 0.5f * v0 * (1.0f + erff(v0 * 0.70710678118654752f));
                g.y = 0.5f * v1 * (1.0f + erff(v1 * 0.70710678118654752f));
                *reinterpret_cast<float2*>(hrow + c) = g;
            }
        }
    }
}

// ---------------------------------------------------------------------------
// ffn2: out[token] += gw * (h @ W2[e] + b2[e])   (K = F_DIM)
// ---------------------------------------------------------------------------
__global__ __launch_bounds__(NTHREADS) void ffn2_kernel(
    const float* __restrict__ W2,
    const float* __restrict__ b2,
    float* __restrict__ out) {
    int e    = blockIdx.y / TILES_PER_E;
    int tile = blockIdx.y % TILES_PER_E;
    int row0 = tile * BM;
    int cnt  = g_cnt[e];
    if (row0 >= cnt) return;
    int off  = g_off[e];
    int col0 = blockIdx.x * BN;
    const float* B = W2 + (size_t)e * F_DIM * H_DIM;
    const float* A = g_h + (size_t)(off + row0) * F_DIM;

    __shared__ uint32_t As[BM * AS_STRIDE];
    __shared__ uint32_t Bs[BK * BS_STRIDE];

    int tid = threadIdx.x;
    int warp = tid >> 5, lane = tid & 31;
    int gid = lane >> 2, tig = lane & 3;
    int wm = (warp >> 2) * 64, wn = (warp & 3) * 32;

    float acc[4][4][4];
#pragma unroll
    for (int mf = 0; mf < 4; mf++)
#pragma unroll
        for (int nf = 0; nf < 4; nf++)
#pragma unroll
            for (int r = 0; r < 4; r++) acc[mf][nf][r] = 0.0f;

    int a_r = tid >> 3, a_c = (tid & 7) * 4;
    int b_r = tid >> 5, b_c = (tid & 31) * 4;

    float4 rA[4], rB[4];

#pragma unroll
    for (int i = 0; i < 4; i++) {
        rA[i] = *reinterpret_cast<const float4*>(A + (size_t)(a_r + i * 32) * F_DIM + a_c);
        rB[i] = *reinterpret_cast<const float4*>(B + (size_t)(b_r + i * 8) * H_DIM + col0 + b_c);
    }
#pragma unroll
    for (int i = 0; i < 4; i++) {
        uint4 va = {f2tf32(rA[i].x), f2tf32(rA[i].y), f2tf32(rA[i].z), f2tf32(rA[i].w)};
        *reinterpret_cast<uint4*>(&As[(a_r + i * 32) * AS_STRIDE + a_c]) = va;
        uint4 vb = {f2tf32(rB[i].x), f2tf32(rB[i].y), f2tf32(rB[i].z), f2tf32(rB[i].w)};
        *reinterpret_cast<uint4*>(&Bs[(b_r + i * 8) * BS_STRIDE + b_c]) = vb;
    }
    __syncthreads();

    const int NKT = F_DIM / BK;
    for (int kt = 0; kt < NKT; kt++) {
        bool more = (kt + 1 < NKT);
        if (more) {
            int k0 = (kt + 1) * BK;
#pragma unroll
            for (int i = 0; i < 4; i++) {
                rA[i] = *reinterpret_cast<const float4*>(A + (size_t)(a_r + i * 32) * F_DIM + k0 + a_c);
                rB[i] = *reinterpret_cast<const float4*>(B + (size_t)(k0 + b_r + i * 8) * H_DIM + col0 + b_c);
            }
        }
#pragma unroll
        for (int ks = 0; ks < 4; ks++) {
            int k = ks * 8;
            uint32_t af[4][4], bf[4][2];
#pragma unroll
            for (int mf = 0; mf < 4; mf++) {
                int m = wm + mf * 16 + gid;
                af[mf][0] = As[m * AS_STRIDE + k + tig];
                af[mf][1] = As[(m + 8) * AS_STRIDE + k + tig];
                af[mf][2] = As[m * AS_STRIDE + k + tig + 4];
                af[mf][3] = As[(m + 8) * AS_STRIDE + k + tig + 4];
            }
#pragma unroll
            for (int nf = 0; nf < 4; nf++) {
                int n = wn + nf * 8 + gid;
                bf[nf][0] = Bs[(k + tig) * BS_STRIDE + n];
                bf[nf][1] = Bs[(k + tig + 4) * BS_STRIDE + n];
            }
#pragma unroll
            for (int mf = 0; mf < 4; mf++)
#pragma unroll
                for (int nf = 0; nf < 4; nf++)
                    mma_tf32(acc[mf][nf], af[mf][0], af[mf][1], af[mf][2], af[mf][3],
                             bf[nf][0], bf[nf][1]);
        }
        if (more) {
            __syncthreads();
#pragma unroll
            for (int i = 0; i < 4; i++) {
                uint4 va = {f2tf32(rA[i].x), f2tf32(rA[i].y), f2tf32(rA[i].z), f2tf32(rA[i].w)};
                *reinterpret_cast<uint4*>(&As[(a_r + i * 32) * AS_STRIDE + a_c]) = va;
                uint4 vb = {f2tf32(rB[i].x), f2tf32(rB[i].y), f2tf32(rB[i].z), f2tf32(rB[i].w)};
                *reinterpret_cast<uint4*>(&Bs[(b_r + i * 8) * BS_STRIDE + b_c]) = vb;
            }
            __syncthreads();
        }
    }

    // epilogue: bias, gate weight, atomic scatter
#pragma unroll
    for (int mf = 0; mf < 4; mf++) {
#pragma unroll
        for (int r2 = 0; r2 < 2; r2++) {
            int m = wm + mf * 16 + gid + r2 * 8;
            int r = row0 + m;
            if (r < cnt) {
                int   token = g_tok[e * N_TOK + r];
                float gw    = g_gw [e * N_TOK + r];
                float* orow = out + (size_t)token * H_DIM + col0;
#pragma unroll
                for (int nf = 0; nf < 4; nf++) {
                    int c = wn + nf * 8 + tig * 2;
                    float v0 = acc[mf][nf][r2 * 2 + 0] + b2[e * H_DIM + col0 + c];
                    float v1 = acc[mf][nf][r2 * 2 + 1] + b2[e * H_DIM + col0 + c + 1];
                    atomicAdd(orow + c,     gw * v0);
                    atomicAdd(orow + c + 1, gw * v1);
                }
            }
        }
    }
}

extern "C" void kernel_launch(void* const* d_in, const int* in_sizes, int n_in,
                              void* d_out, int out_size) {
    const float* x  = (const float*)d_in[0];
    const float* W1 = (const float*)d_in[1];
    const float* b1 = (const float*)d_in[2];
    const float* W2 = (const float*)d_in[3];
    const float* b2 = (const float*)d_in[4];
    const float* Wg = (const float*)d_in[5];
    const float* bg = (const float*)d_in[6];
    float* out = (float*)d_out;

    zero_kernel<<<1024, 256>>>(out, out_size);
    gate_kernel<<<N_TOK / 8, 256>>>(x, Wg, bg);
    offsets_kernel<<<1, 1>>>();
    ffn1_kernel<<<dim3(F_DIM / BN, N_EXP * TILES_PER_E), NTHREADS>>>(x, W1, b1);
    ffn2_kernel<<<dim3(H_DIM / BN, N_EXP * TILES_PER_E), NTHREADS>>>(W2, b2, out);
}

// round 5
// speedup vs baseline: 1.0930x; 1.0930x over previous
#include <cuda_runtime.h>
#include <math.h>
#include <stdint.h>

#define N_TOK 4096
#define H_DIM 1024
#define F_DIM 4096
#define N_EXP 8

#define BM 128
#define BN 256
#define BK 32
#define NTHREADS 256
#define TILES_PER_E 32

#define AS_STRIDE 40     // words; 40 mod 32 = 8 -> banks 8*gid+tig distinct
#define BS_STRIDE 264    // words; 264 mod 32 = 8 -> banks 8*tig+gid distinct
#define A_STAGE_W (BM * AS_STRIDE)          // 5120 words = 20480 B
#define B_STAGE_W (BK * BS_STRIDE)          // 8448 words = 33792 B
#define SMEM_BYTES (512 + 2 * A_STAGE_W * 4 + 2 * B_STAGE_W * 4)  // 109056

// Routing state + h scratch (allocation-free: __device__ globals).
__device__ int   g_cnt[N_EXP];
__device__ int   g_off[N_EXP];
__device__ int   g_tok[N_EXP * N_TOK];
__device__ float g_gw [N_EXP * N_TOK];
__device__ float g_h[(size_t)9216 * F_DIM];

__device__ __forceinline__ uint32_t f2tf32(float f) {
    uint32_t r;
    asm("cvt.rna.tf32.f32 %0, %1;" : "=r"(r) : "f"(f));
    return r;
}
__device__ __forceinline__ void mma_tf32(float c[4],
                                         uint32_t a0, uint32_t a1, uint32_t a2, uint32_t a3,
                                         uint32_t b0, uint32_t b1) {
    asm volatile(
        "mma.sync.aligned.m16n8k8.row.col.f32.tf32.tf32.f32 "
        "{%0,%1,%2,%3}, {%4,%5,%6,%7}, {%8,%9}, {%0,%1,%2,%3};\n"
        : "+f"(c[0]), "+f"(c[1]), "+f"(c[2]), "+f"(c[3])
        : "r"(a0), "r"(a1), "r"(a2), "r"(a3), "r"(b0), "r"(b1));
}
#define CP_ASYNC16(dst, src) \
    asm volatile("cp.async.cg.shared.global [%0], [%1], 16;" :: "r"(dst), "l"(src) : "memory")
#define CP_COMMIT() asm volatile("cp.async.commit_group;" ::: "memory")
#define CP_WAIT0()  asm volatile("cp.async.wait_group 0;" ::: "memory")

__device__ __forceinline__ float gelu_exact(float v) {
    return 0.5f * v * (1.0f + erff(v * 0.70710678118654752f));
}

// ---------------- small kernels ----------------
__global__ void zero_kernel(float* __restrict__ out, int n) {
    int i = blockIdx.x * blockDim.x + threadIdx.x;
    if (i < N_EXP) g_cnt[i] = 0;
    int stride = gridDim.x * blockDim.x;
    for (int j = i; j < n; j += stride) out[j] = 0.0f;
}

__global__ void gate_kernel(const float* __restrict__ x,
                            const float* __restrict__ Wg,
                            const float* __restrict__ bg) {
    int warp = threadIdx.x >> 5, lane = threadIdx.x & 31;
    int n = blockIdx.x * (blockDim.x >> 5) + warp;
    if (n >= N_TOK) return;
    float acc[N_EXP];
#pragma unroll
    for (int e = 0; e < N_EXP; e++) acc[e] = 0.0f;
    const float* xr = x + (size_t)n * H_DIM;
    for (int h = lane; h < H_DIM; h += 32) {
        float xv = xr[h];
        const float4 w0 = *reinterpret_cast<const float4*>(Wg + h * N_EXP);
        const float4 w1 = *reinterpret_cast<const float4*>(Wg + h * N_EXP + 4);
        acc[0] += xv * w0.x; acc[1] += xv * w0.y; acc[2] += xv * w0.z; acc[3] += xv * w0.w;
        acc[4] += xv * w1.x; acc[5] += xv * w1.y; acc[6] += xv * w1.z; acc[7] += xv * w1.w;
    }
#pragma unroll
    for (int e = 0; e < N_EXP; e++)
#pragma unroll
        for (int o = 16; o > 0; o >>= 1) acc[e] += __shfl_xor_sync(0xffffffffu, acc[e], o);
    if (lane == 0) {
        float p[N_EXP], m = -1e30f, s = 0.0f;
#pragma unroll
        for (int e = 0; e < N_EXP; e++) { p[e] = acc[e] + bg[e]; m = fmaxf(m, p[e]); }
#pragma unroll
        for (int e = 0; e < N_EXP; e++) { p[e] = expf(p[e] - m); s += p[e]; }
        float inv = 1.0f / s;
#pragma unroll
        for (int e = 0; e < N_EXP; e++) p[e] *= inv;
        int i0 = 0;
#pragma unroll
        for (int e = 1; e < N_EXP; e++) if (p[e] > p[i0]) i0 = e;
        int i1 = (i0 == 0) ? 1 : 0;
#pragma unroll
        for (int e = 0; e < N_EXP; e++) if (e != i0 && p[e] > p[i1]) i1 = e;
        int p0 = atomicAdd(&g_cnt[i0], 1);
        g_tok[i0 * N_TOK + p0] = n;  g_gw[i0 * N_TOK + p0] = p[i0];
        int p1 = atomicAdd(&g_cnt[i1], 1);
        g_tok[i1 * N_TOK + p1] = n;  g_gw[i1 * N_TOK + p1] = p[i1];
    }
}

__global__ void offsets_kernel() {
    if (threadIdx.x == 0 && blockIdx.x == 0) {
        int off = 0;
        for (int e = 0; e < N_EXP; e++) {
            g_off[e] = off;
            off += ((g_cnt[e] + BM - 1) / BM) * BM;
        }
    }
}

// ---------------------------------------------------------------------------
// Shared GEMM core helpers (macros operate on local names)
// ---------------------------------------------------------------------------
#define DECLARE_TILE_CTX() \
    int tid = threadIdx.x, warp = tid >> 5, lane = tid & 31; \
    int gid = lane >> 2, tig = lane & 3; \
    int wm = (warp >> 2) * 64, wn = (warp & 3) * 64; \
    float acc[4][8][4]; \
    _Pragma("unroll") for (int mf = 0; mf < 4; mf++) \
    _Pragma("unroll") for (int nf = 0; nf < 8; nf++) \
    _Pragma("unroll") for (int r = 0; r < 4; r++) acc[mf][nf][r] = 0.0f;

#define COMPUTE_KTILE(Ast, Bst) do { \
    _Pragma("unroll") \
    for (int ks = 0; ks < 4; ks++) { \
        int k = ks * 8; \
        uint32_t af[4][4], bf[8][2]; \
        _Pragma("unroll") \
        for (int mf = 0; mf < 4; mf++) { \
            int m = wm + mf * 16 + gid; \
            af[mf][0] = f2tf32((Ast)[m * AS_STRIDE + k + tig]); \
            af[mf][1] = f2tf32((Ast)[(m + 8) * AS_STRIDE + k + tig]); \
            af[mf][2] = f2tf32((Ast)[m * AS_STRIDE + k + tig + 4]); \
            af[mf][3] = f2tf32((Ast)[(m + 8) * AS_STRIDE + k + tig + 4]); \
        } \
        _Pragma("unroll") \
        for (int nf = 0; nf < 8; nf++) { \
            int n = wn + nf * 8 + gid; \
            bf[nf][0] = f2tf32((Bst)[(k + tig) * BS_STRIDE + n]); \
            bf[nf][1] = f2tf32((Bst)[(k + tig + 4) * BS_STRIDE + n]); \
        } \
        _Pragma("unroll") \
        for (int mf = 0; mf < 4; mf++) \
        _Pragma("unroll") \
        for (int nf = 0; nf < 8; nf++) \
            mma_tf32(acc[mf][nf], af[mf][0], af[mf][1], af[mf][2], af[mf][3], \
                     bf[nf][0], bf[nf][1]); \
    } } while (0)

// ---------------------------------------------------------------------------
// ffn1: g_h = gelu(X_gathered @ W1[e] + b1[e])   K = H_DIM
// ---------------------------------------------------------------------------
__global__ __launch_bounds__(NTHREADS, 1) void ffn1_kernel(
    const float* __restrict__ x,
    const float* __restrict__ W1,
    const float* __restrict__ b1) {
    extern __shared__ char dsm[];
    int* toks  = (int*)dsm;
    float* As  = (float*)(dsm + 512);
    float* Bs  = (float*)(dsm + 512 + 2 * A_STAGE_W * 4);

    int e    = blockIdx.y >> 5;
    int tile = blockIdx.y & 31;
    int row0 = tile * BM;
    int cnt  = g_cnt[e];
    if (row0 >= cnt) return;
    int off  = g_off[e];
    int col0 = blockIdx.x * BN;
    const float* B = W1 + (size_t)e * H_DIM * F_DIM;

    DECLARE_TILE_CTX();

    if (tid < BM) {
        int r = row0 + tid; if (r >= cnt) r = cnt - 1;
        toks[tid] = g_tok[e * N_TOK + r];
    }
    __syncthreads();

    // per-thread cp.async slots
    int a_rw = tid >> 3, a_c4 = tid & 7;                 // A: 4 rows (a_rw + 32i)
    uint32_t a_dst[4]; const float* a_src[4];
#pragma unroll
    for (int i = 0; i < 4; i++) {
        int rw = a_rw + i * 32;
        a_dst[i] = (uint32_t)__cvta_generic_to_shared(As + rw * AS_STRIDE + a_c4 * 4);
        a_src[i] = x + (size_t)toks[rw] * H_DIM + a_c4 * 4;
    }
    int b_k = tid >> 6, b_n4 = tid & 63;                 // B: 8 k-rows (b_k + 4i)
    uint32_t b_dst[8]; const float* b_src[8];
#pragma unroll
    for (int i = 0; i < 8; i++) {
        int kk = b_k + i * 4;
        b_dst[i] = (uint32_t)__cvta_generic_to_shared(Bs + kk * BS_STRIDE + b_n4 * 4);
        b_src[i] = B + (size_t)kk * F_DIM + col0 + b_n4 * 4;
    }

#define FILL1(st, k0) do { \
    _Pragma("unroll") for (int i = 0; i < 4; i++) \
        CP_ASYNC16(a_dst[i] + (st) * (A_STAGE_W * 4), a_src[i] + (k0)); \
    _Pragma("unroll") for (int i = 0; i < 8; i++) \
        CP_ASYNC16(b_dst[i] + (st) * (B_STAGE_W * 4), b_src[i] + (size_t)(k0) * F_DIM); \
    CP_COMMIT(); } while (0)

    FILL1(0, 0);
    const int NKT = H_DIM / BK;
    for (int kt = 0; kt < NKT; kt++) {
        CP_WAIT0();
        __syncthreads();
        if (kt + 1 < NKT) FILL1((kt + 1) & 1, (kt + 1) * BK);
        const float* Ast = As + (kt & 1) * A_STAGE_W;
        const float* Bst = Bs + (kt & 1) * B_STAGE_W;
        COMPUTE_KTILE(Ast, Bst);
        __syncthreads();
    }

    // epilogue: bias + exact gelu -> g_h
#pragma unroll
    for (int mf = 0; mf < 4; mf++) {
#pragma unroll
        for (int r2 = 0; r2 < 2; r2++) {
            int m = wm + mf * 16 + gid + r2 * 8;
            float* hrow = g_h + (size_t)(off + row0 + m) * F_DIM + col0;
#pragma unroll
            for (int nf = 0; nf < 8; nf++) {
                int c = wn + nf * 8 + tig * 2;
                float v0 = acc[mf][nf][r2 * 2 + 0] + b1[e * F_DIM + col0 + c];
                float v1 = acc[mf][nf][r2 * 2 + 1] + b1[e * F_DIM + col0 + c + 1];
                float2 g = {gelu_exact(v0), gelu_exact(v1)};
                *reinterpret_cast<float2*>(hrow + c) = g;
            }
        }
    }
}

// ---------------------------------------------------------------------------
// ffn2: out[token] += gw * (h @ W2[e] + b2[e])   K = F_DIM
// ---------------------------------------------------------------------------
__global__ __launch_bounds__(NTHREADS, 1) void ffn2_kernel(
    const float* __restrict__ W2,
    const float* __restrict__ b2,
    float* __restrict__ out) {
    extern __shared__ char dsm[];
    float* As  = (float*)(dsm + 512);
    float* Bs  = (float*)(dsm + 512 + 2 * A_STAGE_W * 4);

    int e    = blockIdx.y >> 5;
    int tile = blockIdx.y & 31;
    int row0 = tile * BM;
    int cnt  = g_cnt[e];
    if (row0 >= cnt) return;
    int off  = g_off[e];
    int col0 = blockIdx.x * BN;
    const float* B = W2 + (size_t)e * F_DIM * H_DIM;
    const float* A = g_h + (size_t)(off + row0) * F_DIM;

    DECLARE_TILE_CTX();

    int a_rw = tid >> 3, a_c4 = tid & 7;
    uint32_t a_dst[4]; const float* a_src[4];
#pragma unroll
    for (int i = 0; i < 4; i++) {
        int rw = a_rw + i * 32;
        a_dst[i] = (uint32_t)__cvta_generic_to_shared(As + rw * AS_STRIDE + a_c4 * 4);
        a_src[i] = A + (size_t)rw * F_DIM + a_c4 * 4;
    }
    int b_k = tid >> 6, b_n4 = tid & 63;
    uint32_t b_dst[8]; const float* b_src[8];
#pragma unroll
    for (int i = 0; i < 8; i++) {
        int kk = b_k + i * 4;
        b_dst[i] = (uint32_t)__cvta_generic_to_shared(Bs + kk * BS_STRIDE + b_n4 * 4);
        b_src[i] = B + (size_t)kk * H_DIM + col0 + b_n4 * 4;
    }

#define FILL2(st, k0) do { \
    _Pragma("unroll") for (int i = 0; i < 4; i++) \
        CP_ASYNC16(a_dst[i] + (st) * (A_STAGE_W * 4), a_src[i] + (k0)); \
    _Pragma("unroll") for (int i = 0; i < 8; i++) \
        CP_ASYNC16(b_dst[i] + (st) * (B_STAGE_W * 4), b_src[i] + (size_t)(k0) * H_DIM); \
    CP_COMMIT(); } while (0)

    FILL2(0, 0);
    const int NKT = F_DIM / BK;
    for (int kt = 0; kt < NKT; kt++) {
        CP_WAIT0();
        __syncthreads();
        if (kt + 1 < NKT) FILL2((kt + 1) & 1, (kt + 1) * BK);
        const float* Ast = As + (kt & 1) * A_STAGE_W;
        const float* Bst = Bs + (kt & 1) * B_STAGE_W;
        COMPUTE_KTILE(Ast, Bst);
        __syncthreads();
    }

    // epilogue: bias, gate weight, atomic scatter
#pragma unroll
    for (int mf = 0; mf < 4; mf++) {
#pragma unroll
        for (int r2 = 0; r2 < 2; r2++) {
            int m = wm + mf * 16 + gid + r2 * 8;
            int r = row0 + m;
            if (r < cnt) {
                int   token = g_tok[e * N_TOK + r];
                float gw    = g_gw [e * N_TOK + r];
                float* orow = out + (size_t)token * H_DIM + col0;
#pragma unroll
                for (int nf = 0; nf < 8; nf++) {
                    int c = wn + nf * 8 + tig * 2;
                    float v0 = acc[mf][nf][r2 * 2 + 0] + b2[e * H_DIM + col0 + c];
                    float v1 = acc[mf][nf][r2 * 2 + 1] + b2[e * H_DIM + col0 + c + 1];
                    atomicAdd(orow + c,     gw * v0);
                    atomicAdd(orow + c + 1, gw * v1);
                }
            }
        }
    }
}

extern "C" void kernel_launch(void* const* d_in, const int* in_sizes, int n_in,
                              void* d_out, int out_size) {
    const float* x  = (const float*)d_in[0];
    const float* W1 = (const float*)d_in[1];
    const float* b1 = (const float*)d_in[2];
    const float* W2 = (const float*)d_in[3];
    const float* b2 = (const float*)d_in[4];
    const float* Wg = (const float*)d_in[5];
    const float* bg = (const float*)d_in[6];
    float* out = (float*)d_out;

    cudaFuncSetAttribute(ffn1_kernel, cudaFuncAttributeMaxDynamicSharedMemorySize, SMEM_BYTES);
    cudaFuncSetAttribute(ffn2_kernel, cudaFuncAttributeMaxDynamicSharedMemorySize, SMEM_BYTES);

    zero_kernel<<<1024, 256>>>(out, out_size);
    gate_kernel<<<N_TOK / 8, 256>>>(x, Wg, bg);
    offsets_kernel<<<1, 1>>>();
    ffn1_kernel<<<dim3(F_DIM / BN, N_EXP * TILES_PER_E), NTHREADS, SMEM_BYTES>>>(x, W1, b1);
    ffn2_kernel<<<dim3(H_DIM / BN, N_EXP * TILES_PER_E), NTHREADS, SMEM_BYTES>>>(W2, b2, out);
}

// round 6
// speedup vs baseline: 1.1449x; 1.0475x over previous
#include <cuda_runtime.h>
#include <math.h>
#include <stdint.h>

#define N_TOK 4096
#define H_DIM 1024
#define F_DIM 4096
#define N_EXP 8

#define BM 128
#define BN 256
#define BK 32
#define NTHREADS 256
#define TILES_PER_E 32

#define AS_STRIDE 36     // bank = (4*gid+tig) mod 32 -> all 32 distinct
#define BS_STRIDE 264    // bank = (8*tig+gid) mod 32 -> all 32 distinct
#define A_STAGE_W (BM * AS_STRIDE)          // 4608 words = 18432 B
#define B_STAGE_W (BK * BS_STRIDE)          // 8448 words = 33792 B
#define SMEM_BYTES (512 + 2 * A_STAGE_W * 4 + 2 * B_STAGE_W * 4)  // 104960

// Routing state + scratch (allocation-free: __device__ globals).
__device__ int      g_cnt[N_EXP];
__device__ int      g_off[N_EXP];
__device__ int      g_tok[N_EXP * N_TOK];
__device__ float    g_gw [N_EXP * N_TOK];
__device__ unsigned g_xt[(size_t)N_TOK * H_DIM];       // x as tf32 bits
__device__ unsigned g_h[(size_t)9216 * F_DIM];          // gelu(h) as tf32 bits

__device__ __forceinline__ uint32_t f2tf32(float f) {
    uint32_t r;
    asm("cvt.rna.tf32.f32 %0, %1;" : "=r"(r) : "f"(f));
    return r;
}
__device__ __forceinline__ void mma_tf32(float c[4],
                                         uint32_t a0, uint32_t a1, uint32_t a2, uint32_t a3,
                                         uint32_t b0, uint32_t b1) {
    asm volatile(
        "mma.sync.aligned.m16n8k8.row.col.f32.tf32.tf32.f32 "
        "{%0,%1,%2,%3}, {%4,%5,%6,%7}, {%8,%9}, {%0,%1,%2,%3};\n"
        : "+f"(c[0]), "+f"(c[1]), "+f"(c[2]), "+f"(c[3])
        : "r"(a0), "r"(a1), "r"(a2), "r"(a3), "r"(b0), "r"(b1));
}
#define CP_ASYNC16(dst, src) \
    asm volatile("cp.async.cg.shared.global [%0], [%1], 16;" :: "r"(dst), "l"(src) : "memory")
#define CP_COMMIT() asm volatile("cp.async.commit_group;" ::: "memory")
#define CP_WAIT0()  asm volatile("cp.async.wait_group 0;" ::: "memory")

__device__ __forceinline__ float gelu_exact(float v) {
    return 0.5f * v * (1.0f + erff(v * 0.70710678118654752f));
}

// ---------------- small kernels ----------------
__global__ void zero_kernel(float* __restrict__ out, int n) {
    int i = blockIdx.x * blockDim.x + threadIdx.x;
    if (i < N_EXP) g_cnt[i] = 0;
    int stride = gridDim.x * blockDim.x;
    for (int j = i; j < n; j += stride) out[j] = 0.0f;
}

__global__ void xconv_kernel(const float* __restrict__ x) {
    int i = blockIdx.x * blockDim.x + threadIdx.x;
    float4 v = reinterpret_cast<const float4*>(x)[i];
    uint4 o = {f2tf32(v.x), f2tf32(v.y), f2tf32(v.z), f2tf32(v.w)};
    reinterpret_cast<uint4*>(g_xt)[i] = o;
}

__global__ void gate_kernel(const float* __restrict__ x,
                            const float* __restrict__ Wg,
                            const float* __restrict__ bg) {
    int warp = threadIdx.x >> 5, lane = threadIdx.x & 31;
    int n = blockIdx.x * (blockDim.x >> 5) + warp;
    if (n >= N_TOK) return;
    float acc[N_EXP];
#pragma unroll
    for (int e = 0; e < N_EXP; e++) acc[e] = 0.0f;
    const float* xr = x + (size_t)n * H_DIM;
    for (int h = lane; h < H_DIM; h += 32) {
        float xv = xr[h];
        const float4 w0 = *reinterpret_cast<const float4*>(Wg + h * N_EXP);
        const float4 w1 = *reinterpret_cast<const float4*>(Wg + h * N_EXP + 4);
        acc[0] += xv * w0.x; acc[1] += xv * w0.y; acc[2] += xv * w0.z; acc[3] += xv * w0.w;
        acc[4] += xv * w1.x; acc[5] += xv * w1.y; acc[6] += xv * w1.z; acc[7] += xv * w1.w;
    }
#pragma unroll
    for (int e = 0; e < N_EXP; e++)
#pragma unroll
        for (int o = 16; o > 0; o >>= 1) acc[e] += __shfl_xor_sync(0xffffffffu, acc[e], o);
    if (lane == 0) {
        float p[N_EXP], m = -1e30f, s = 0.0f;
#pragma unroll
        for (int e = 0; e < N_EXP; e++) { p[e] = acc[e] + bg[e]; m = fmaxf(m, p[e]); }
#pragma unroll
        for (int e = 0; e < N_EXP; e++) { p[e] = expf(p[e] - m); s += p[e]; }
        float inv = 1.0f / s;
#pragma unroll
        for (int e = 0; e < N_EXP; e++) p[e] *= inv;
        int i0 = 0;
#pragma unroll
        for (int e = 1; e < N_EXP; e++) if (p[e] > p[i0]) i0 = e;
        int i1 = (i0 == 0) ? 1 : 0;
#pragma unroll
        for (int e = 0; e < N_EXP; e++) if (e != i0 && p[e] > p[i1]) i1 = e;
        int p0 = atomicAdd(&g_cnt[i0], 1);
        g_tok[i0 * N_TOK + p0] = n;  g_gw[i0 * N_TOK + p0] = p[i0];
        int p1 = atomicAdd(&g_cnt[i1], 1);
        g_tok[i1 * N_TOK + p1] = n;  g_gw[i1 * N_TOK + p1] = p[i1];
    }
}

__global__ void offsets_kernel() {
    if (threadIdx.x == 0 && blockIdx.x == 0) {
        int off = 0;
        for (int e = 0; e < N_EXP; e++) {
            g_off[e] = off;
            off += ((g_cnt[e] + BM - 1) / BM) * BM;
        }
    }
}

// ---------------------------------------------------------------------------
// GEMM core: 8 warps of 64x64, A tf32-bits in smem, B fp32 in smem (cvt on load)
// ---------------------------------------------------------------------------
#define DECLARE_TILE_CTX() \
    int tid = threadIdx.x, warp = tid >> 5, lane = tid & 31; \
    int gid = lane >> 2, tig = lane & 3; \
    int wm = (warp >> 2) * 64, wn = (warp & 3) * 64; \
    float acc[4][8][4]; \
    _Pragma("unroll") for (int mf = 0; mf < 4; mf++) \
    _Pragma("unroll") for (int nf = 0; nf < 8; nf++) \
    _Pragma("unroll") for (int r = 0; r < 4; r++) acc[mf][nf][r] = 0.0f;

#define LOAD_AFRAG(dst, Ast, k) do { \
    _Pragma("unroll") \
    for (int mf = 0; mf < 4; mf++) { \
        int m = wm + mf * 16 + gid; \
        (dst)[mf][0] = (Ast)[m * AS_STRIDE + (k) + tig]; \
        (dst)[mf][1] = (Ast)[(m + 8) * AS_STRIDE + (k) + tig]; \
        (dst)[mf][2] = (Ast)[m * AS_STRIDE + (k) + tig + 4]; \
        (dst)[mf][3] = (Ast)[(m + 8) * AS_STRIDE + (k) + tig + 4]; \
    } } while (0)

#define LOAD_BFRAG(dst, Bst, k) do { \
    _Pragma("unroll") \
    for (int nf = 0; nf < 8; nf++) { \
        int n = wn + nf * 8 + gid; \
        (dst)[nf][0] = f2tf32((Bst)[((k) + tig) * BS_STRIDE + n]); \
        (dst)[nf][1] = f2tf32((Bst)[((k) + tig + 4) * BS_STRIDE + n]); \
    } } while (0)

#define COMPUTE_KTILE(Ast, Bst) do { \
    uint32_t af[2][4][4], bf[2][8][2]; \
    LOAD_AFRAG(af[0], Ast, 0); \
    LOAD_BFRAG(bf[0], Bst, 0); \
    _Pragma("unroll") \
    for (int ks = 0; ks < 4; ks++) { \
        int cb = ks & 1, nb = cb ^ 1; \
        if (ks < 3) { \
            LOAD_AFRAG(af[nb], Ast, (ks + 1) * 8); \
            LOAD_BFRAG(bf[nb], Bst, (ks + 1) * 8); \
        } \
        _Pragma("unroll") \
        for (int mf = 0; mf < 4; mf++) \
        _Pragma("unroll") \
        for (int nf = 0; nf < 8; nf++) \
            mma_tf32(acc[mf][nf], af[cb][mf][0], af[cb][mf][1], af[cb][mf][2], af[cb][mf][3], \
                     bf[cb][nf][0], bf[cb][nf][1]); \
    } } while (0)

// ---------------------------------------------------------------------------
// ffn1: g_h = tf32(gelu(X_gathered @ W1[e] + b1[e]))   K = H_DIM
// ---------------------------------------------------------------------------
__global__ __launch_bounds__(NTHREADS, 1) void ffn1_kernel(
    const float* __restrict__ W1,
    const float* __restrict__ b1) {
    extern __shared__ char dsm[];
    int* toks     = (int*)dsm;
    unsigned* As  = (unsigned*)(dsm + 512);
    float* Bs     = (float*)(dsm + 512 + 2 * A_STAGE_W * 4);

    int e    = blockIdx.y >> 5;
    int tile = blockIdx.y & 31;
    int row0 = tile * BM;
    int cnt  = g_cnt[e];
    if (row0 >= cnt) return;
    int off  = g_off[e];
    int col0 = blockIdx.x * BN;
    const float* B = W1 + (size_t)e * H_DIM * F_DIM;

    DECLARE_TILE_CTX();

    if (tid < BM) {
        int r = row0 + tid; if (r >= cnt) r = cnt - 1;
        toks[tid] = g_tok[e * N_TOK + r];
    }
    __syncthreads();

    int a_rw = tid >> 3, a_c4 = tid & 7;
    uint32_t a_dst[4]; const unsigned* a_src[4];
#pragma unroll
    for (int i = 0; i < 4; i++) {
        int rw = a_rw + i * 32;
        a_dst[i] = (uint32_t)__cvta_generic_to_shared(As + rw * AS_STRIDE + a_c4 * 4);
        a_src[i] = g_xt + (size_t)toks[rw] * H_DIM + a_c4 * 4;
    }
    int b_k = tid >> 6, b_n4 = tid & 63;
    uint32_t b_dst[8]; const float* b_src[8];
#pragma unroll
    for (int i = 0; i < 8; i++) {
        int kk = b_k + i * 4;
        b_dst[i] = (uint32_t)__cvta_generic_to_shared(Bs + kk * BS_STRIDE + b_n4 * 4);
        b_src[i] = B + (size_t)kk * F_DIM + col0 + b_n4 * 4;
    }

#define FILL1(st, k0) do { \
    _Pragma("unroll") for (int i = 0; i < 4; i++) \
        CP_ASYNC16(a_dst[i] + (st) * (A_STAGE_W * 4), a_src[i] + (k0)); \
    _Pragma("unroll") for (int i = 0; i < 8; i++) \
        CP_ASYNC16(b_dst[i] + (st) * (B_STAGE_W * 4), b_src[i] + (size_t)(k0) * F_DIM); \
    CP_COMMIT(); } while (0)

    FILL1(0, 0);
    const int NKT = H_DIM / BK;
    for (int kt = 0; kt < NKT; kt++) {
        CP_WAIT0();
        __syncthreads();
        if (kt + 1 < NKT) FILL1((kt + 1) & 1, (kt + 1) * BK);
        const unsigned* Ast = As + (kt & 1) * A_STAGE_W;
        const float*    Bst = Bs + (kt & 1) * B_STAGE_W;
        COMPUTE_KTILE(Ast, Bst);
        __syncthreads();
    }

    // epilogue: bias + exact gelu -> g_h (tf32 bits)
#pragma unroll
    for (int mf = 0; mf < 4; mf++) {
#pragma unroll
        for (int r2 = 0; r2 < 2; r2++) {
            int m = wm + mf * 16 + gid + r2 * 8;
            unsigned* hrow = g_h + (size_t)(off + row0 + m) * F_DIM + col0;
#pragma unroll
            for (int nf = 0; nf < 8; nf++) {
                int c = wn + nf * 8 + tig * 2;
                float v0 = acc[mf][nf][r2 * 2 + 0] + b1[e * F_DIM + col0 + c];
                float v1 = acc[mf][nf][r2 * 2 + 1] + b1[e * F_DIM + col0 + c + 1];
                uint2 g = {f2tf32(gelu_exact(v0)), f2tf32(gelu_exact(v1))};
                *reinterpret_cast<uint2*>(hrow + c) = g;
            }
        }
    }
}

// ---------------------------------------------------------------------------
// ffn2: out[token] += gw * (h @ W2[e] + b2[e])   K = F_DIM
// ---------------------------------------------------------------------------
__global__ __launch_bounds__(NTHREADS, 1) void ffn2_kernel(
    const float* __restrict__ W2,
    const float* __restrict__ b2,
    float* __restrict__ out) {
    extern __shared__ char dsm[];
    unsigned* As  = (unsigned*)(dsm + 512);
    float* Bs     = (float*)(dsm + 512 + 2 * A_STAGE_W * 4);

    int e    = blockIdx.y >> 5;
    int tile = blockIdx.y & 31;
    int row0 = tile * BM;
    int cnt  = g_cnt[e];
    if (row0 >= cnt) return;
    int off  = g_off[e];
    int col0 = blockIdx.x * BN;
    const float* B = W2 + (size_t)e * F_DIM * H_DIM;
    const unsigned* A = g_h + (size_t)(off + row0) * F_DIM;

    DECLARE_TILE_CTX();

    int a_rw = tid >> 3, a_c4 = tid & 7;
    uint32_t a_dst[4]; const unsigned* a_src[4];
#pragma unroll
    for (int i = 0; i < 4; i++) {
        int rw = a_rw + i * 32;
        a_dst[i] = (uint32_t)__cvta_generic_to_shared(As + rw * AS_STRIDE + a_c4 * 4);
        a_src[i] = A + (size_t)rw * F_DIM + a_c4 * 4;
    }
    int b_k = tid >> 6, b_n4 = tid & 63;
    uint32_t b_dst[8]; const float* b_src[8];
#pragma unroll
    for (int i = 0; i < 8; i++) {
        int kk = b_k + i * 4;
        b_dst[i] = (uint32_t)__cvta_generic_to_shared(Bs + kk * BS_STRIDE + b_n4 * 4);
        b_src[i] = B + (size_t)kk * H_DIM + col0 + b_n4 * 4;
    }

#define FILL2(st, k0) do { \
    _Pragma("unroll") for (int i = 0; i < 4; i++) \
        CP_ASYNC16(a_dst[i] + (st) * (A_STAGE_W * 4), a_src[i] + (k0)); \
    _Pragma("unroll") for (int i = 0; i < 8; i++) \
        CP_ASYNC16(b_dst[i] + (st) * (B_STAGE_W * 4), b_src[i] + (size_t)(k0) * H_DIM); \
    CP_COMMIT(); } while (0)

    FILL2(0, 0);
    const int NKT = F_DIM / BK;
    for (int kt = 0; kt < NKT; kt++) {
        CP_WAIT0();
        __syncthreads();
        if (kt + 1 < NKT) FILL2((kt + 1) & 1, (kt + 1) * BK);
        const unsigned* Ast = As + (kt & 1) * A_STAGE_W;
        const float*    Bst = Bs + (kt & 1) * B_STAGE_W;
        COMPUTE_KTILE(Ast, Bst);
        __syncthreads();
    }

    // epilogue: bias, gate weight, atomic scatter
#pragma unroll
    for (int mf = 0; mf < 4; mf++) {
#pragma unroll
        for (int r2 = 0; r2 < 2; r2++) {
            int m = wm + mf * 16 + gid + r2 * 8;
            int r = row0 + m;
            if (r < cnt) {
                int   token = g_tok[e * N_TOK + r];
                float gw    = g_gw [e * N_TOK + r];
                float* orow = out + (size_t)token * H_DIM + col0;
#pragma unroll
                for (int nf = 0; nf < 8; nf++) {
                    int c = wn + nf * 8 + tig * 2;
                    float v0 = acc[mf][nf][r2 * 2 + 0] + b2[e * H_DIM + col0 + c];
                    float v1 = acc[mf][nf][r2 * 2 + 1] + b2[e * H_DIM + col0 + c + 1];
                    atomicAdd(orow + c,     gw * v0);
                    atomicAdd(orow + c + 1, gw * v1);
                }
            }
        }
    }
}

extern "C" void kernel_launch(void* const* d_in, const int* in_sizes, int n_in,
                              void* d_out, int out_size) {
    const float* x  = (const float*)d_in[0];
    const float* W1 = (const float*)d_in[1];
    const float* b1 = (const float*)d_in[2];
    const float* W2 = (const float*)d_in[3];
    const float* b2 = (const float*)d_in[4];
    const float* Wg = (const float*)d_in[5];
    const float* bg = (const float*)d_in[6];
    float* out = (float*)d_out;

    cudaFuncSetAttribute(ffn1_kernel, cudaFuncAttributeMaxDynamicSharedMemorySize, SMEM_BYTES);
    cudaFuncSetAttribute(ffn2_kernel, cudaFuncAttributeMaxDynamicSharedMemorySize, SMEM_BYTES);

    zero_kernel<<<1024, 256>>>(out, out_size);
    xconv_kernel<<<(N_TOK * H_DIM / 4) / 256, 256>>>(x);
    gate_kernel<<<N_TOK / 8, 256>>>(x, Wg, bg);
    offsets_kernel<<<1, 1>>>();
    ffn1_kernel<<<dim3(F_DIM / BN, N_EXP * TILES_PER_E), NTHREADS, SMEM_BYTES>>>(W1, b1);
    ffn2_kernel<<<dim3(H_DIM / BN, N_EXP * TILES_PER_E), NTHREADS, SMEM_BYTES>>>(W2, b2, out);
}